// round 4
// baseline (speedup 1.0000x reference)
#include <cuda_runtime.h>
#include <cuda_fp16.h>
#include <cstdint>

// Problem dims (fixed by the dataset)
#define MDIM 4096
#define NDIM 4096
#define KDIM 4096
#define GS   128

// ---------------- scratch (allocation-free rule: __device__ globals) --------
__device__ __half g_Ah[(size_t)MDIM * KDIM];   // A in fp16, row-major [M,K]
__device__ __half g_Wt[(size_t)NDIM * KDIM];   // W^T in fp16, row-major [N,K]

// ---------------- helpers ----------------------------------------------------
__device__ __forceinline__ uint32_t smem_u32(const void* p) {
    uint32_t a;
    asm("{ .reg .u64 t; cvta.to.shared.u64 t, %1; cvt.u32.u64 %0, t; }"
        : "=r"(a) : "l"(p));
    return a;
}

__device__ __forceinline__ uint32_t sw128(uint32_t o) {
    return o ^ ((o >> 3) & 0x70);
}

#define CP_ASYNC16(dst, src) \
    asm volatile("cp.async.cg.shared.global [%0], [%1], 16;" :: "r"(dst), "l"(src) : "memory")
#define CP_COMMIT() asm volatile("cp.async.commit_group;" ::: "memory")
template <int N>
__device__ __forceinline__ void cp_wait() {
    asm volatile("cp.async.wait_group %0;" :: "n"(N) : "memory");
}

__device__ __forceinline__ void ldsm_x4(uint32_t (&r)[4], uint32_t addr) {
    asm volatile("ldmatrix.sync.aligned.m8n8.x4.shared.b16 {%0,%1,%2,%3}, [%4];"
                 : "=r"(r[0]), "=r"(r[1]), "=r"(r[2]), "=r"(r[3]) : "r"(addr));
}

__device__ __forceinline__ void mma_16816(float (&d)[4], const uint32_t (&a)[4],
                                          const uint32_t b0, const uint32_t b1) {
    asm volatile(
        "mma.sync.aligned.m16n8k16.row.col.f32.f16.f16.f32 "
        "{%0,%1,%2,%3}, {%4,%5,%6,%7}, {%8,%9}, {%0,%1,%2,%3};"
        : "+f"(d[0]), "+f"(d[1]), "+f"(d[2]), "+f"(d[3])
        : "r"(a[0]), "r"(a[1]), "r"(a[2]), "r"(a[3]), "r"(b0), "r"(b1));
}

// ---------------- kernel 1: A fp32 -> fp16 ----------------------------------
__global__ void __launch_bounds__(256) convert_A_kernel(const float4* __restrict__ A) {
    size_t i = (size_t)blockIdx.x * blockDim.x + threadIdx.x;  // 2M threads, 8 floats each
    float4 f0 = A[2 * i];
    float4 f1 = A[2 * i + 1];
    __half2 h[4];
    h[0] = __floats2half2_rn(f0.x, f0.y);
    h[1] = __floats2half2_rn(f0.z, f0.w);
    h[2] = __floats2half2_rn(f1.x, f1.y);
    h[3] = __floats2half2_rn(f1.z, f1.w);
    *reinterpret_cast<uint4*>(g_Ah + 8 * i) = *reinterpret_cast<uint4*>(h);
}

// ---------------- kernel 2: dequant + transpose to Wt[n][k] fp16 ------------
__global__ void __launch_bounds__(256) dequant_W_kernel(const int* __restrict__ q,
                                                        const float* __restrict__ s) {
    __shared__ float s_sc[64];
    __shared__ __half s_t[64][72];  // [n_local][k_local], padded

    int k0 = blockIdx.x * 64;
    int n0 = blockIdx.y * 64;
    int t = threadIdx.x;

    if (t < 64) s_sc[t] = s[(size_t)(k0 / GS) * NDIM + n0 + t];
    __syncthreads();

    // 64 k-rows x 8 q-words (8 nibbles each) = 512 words; 2 per thread
    #pragma unroll
    for (int it = 0; it < 2; it++) {
        int v = t + it * 256;
        int kl = v >> 3;
        int w = v & 7;
        uint32_t qw = (uint32_t)q[(size_t)(k0 + kl) * (NDIM / 8) + (n0 >> 3) + w];
        #pragma unroll
        for (int b = 0; b < 8; b++) {
            int nib = (int)((qw >> (4 * b)) & 0xFu);
            float val = (float)(nib - 8) * s_sc[w * 8 + b];
            s_t[w * 8 + b][kl] = __float2half_rn(val);
        }
    }
    __syncthreads();

    // coalesced write of Wt rows: 64 rows x 128B; each thread writes 32B
    int nl = t >> 2;
    int c = (t & 3) * 16;
    const uint4* src = reinterpret_cast<const uint4*>(&s_t[nl][c]);
    uint4* dst = reinterpret_cast<uint4*>(&g_Wt[(size_t)(n0 + nl) * KDIM + k0 + c]);
    dst[0] = src[0];
    dst[1] = src[1];
}

// ---------------- kernel 3: HMMA f16 GEMM ------------------------------------
// CTA tile 128(M) x 256(N), BK=64, 3-stage cp.async pipeline, 8 warps (64x64 each).
static constexpr int BM = 128;
static constexpr int BN = 256;
static constexpr int BK = 64;
static constexpr int NSTAGES = 3;
static constexpr int NCHUNK = KDIM / BK;               // 64
static constexpr int A_TILE_BYTES = BM * BK * 2;       // 16 KB
static constexpr int B_TILE_BYTES = BN * BK * 2;       // 32 KB
static constexpr uint32_t STAGE_BYTES = A_TILE_BYTES + B_TILE_BYTES;  // 48 KB
static constexpr uint32_t SMEM_TOTAL = NSTAGES * STAGE_BYTES;         // 144 KB

// Load one stage: A rows m0..m0+127 and B rows n0..n0+255, 64 halfs (128B) per row.
__device__ __forceinline__ void load_stage(uint32_t sb, int stage, int chunk,
                                           int m0, int n0, int t) {
    uint32_t a_s = sb + stage * STAGE_BYTES;
    uint32_t b_s = a_s + A_TILE_BYTES;
    size_t kbase = (size_t)chunk * BK;
    #pragma unroll
    for (int j = 0; j < 4; j++) {          // A: 1024 x 16B chunks
        int v = t + 256 * j;
        int r = v >> 3;
        int c = v & 7;
        uint32_t off = sw128((uint32_t)(r * 128 + c * 16));
        CP_ASYNC16(a_s + off, g_Ah + (size_t)(m0 + r) * KDIM + kbase + c * 8);
    }
    #pragma unroll
    for (int j = 0; j < 8; j++) {          // B: 2048 x 16B chunks
        int v = t + 256 * j;
        int r = v >> 3;                    // 0..255
        int c = v & 7;
        uint32_t off = sw128((uint32_t)(r * 128 + c * 16));
        CP_ASYNC16(b_s + off, g_Wt + (size_t)(n0 + r) * KDIM + kbase + c * 8);
    }
}

__global__ void __launch_bounds__(256, 1)
gemm_kernel(float* __restrict__ out) {
    extern __shared__ char smem[];
    uint32_t sb = smem_u32(smem);
    int t = threadIdx.x;
    int wid = t >> 5;
    int lane = t & 31;
    int n0 = blockIdx.x * BN;
    int m0 = blockIdx.y * BM;

    // warp tiling: 2 (M) x 4 (N) warps; warp tile 64 x 64
    int warpM = (wid & 1) * 64;
    int warpN = (wid >> 1) * 64;

    // per-lane ldmatrix address components
    int tt = lane >> 3;        // matrix index within x4
    int lr = lane & 7;         // row within 8x8 matrix
    // A frag x4: tiles (m+0,k+0),(m+8,k+0),(m+0,k+16B),(m+8,k+16B)
    int arow = warpM + (tt & 1) * 8 + lr;
    int akoff = (tt >> 1) * 16;       // bytes
    // B frag x4: tiles (n+0,k+0),(n+0,k+16B),(n+8,k+0),(n+8,k+16B)
    int brow = warpN + (tt >> 1) * 8 + lr;
    int bkoff = (tt & 1) * 16;        // bytes

    float acc[4][8][4];
    #pragma unroll
    for (int mi = 0; mi < 4; mi++)
        #pragma unroll
        for (int ni = 0; ni < 8; ni++)
            #pragma unroll
            for (int e = 0; e < 4; e++) acc[mi][ni][e] = 0.0f;

    // prologue: fill NSTAGES-1 stages
    #pragma unroll
    for (int i = 0; i < NSTAGES - 1; i++) {
        load_stage(sb, i, i, m0, n0, t);
        CP_COMMIT();
    }

    int stage = 0;
    for (int i = 0; i < NCHUNK; i++) {
        int pf = i + NSTAGES - 1;
        if (pf < NCHUNK) {
            int pstage = pf - (pf / NSTAGES) * NSTAGES;
            load_stage(sb, pstage, pf, m0, n0, t);
        }
        CP_COMMIT();
        cp_wait<NSTAGES - 1>();   // chunk i resident
        __syncthreads();

        uint32_t a_s = sb + stage * STAGE_BYTES;
        uint32_t b_s = a_s + A_TILE_BYTES;

        #pragma unroll
        for (int kk = 0; kk < 4; kk++) {
            uint32_t afrag[4][4];
            #pragma unroll
            for (int mi = 0; mi < 4; mi++) {
                uint32_t off = sw128((uint32_t)((arow + mi * 16) * 128 + kk * 32 + akoff));
                ldsm_x4(afrag[mi], a_s + off);
            }
            uint32_t bfrag[4][4];
            #pragma unroll
            for (int np = 0; np < 4; np++) {
                uint32_t off = sw128((uint32_t)((brow + np * 16) * 128 + kk * 32 + bkoff));
                ldsm_x4(bfrag[np], b_s + off);
            }
            #pragma unroll
            for (int mi = 0; mi < 4; mi++) {
                #pragma unroll
                for (int ni = 0; ni < 8; ni++) {
                    mma_16816(acc[mi][ni], afrag[mi],
                              bfrag[ni >> 1][(ni & 1) * 2],
                              bfrag[ni >> 1][(ni & 1) * 2 + 1]);
                }
            }
        }
        __syncthreads();

        stage++;
        if (stage == NSTAGES) stage = 0;
    }

    // epilogue: direct gmem writes (accum layout: c0,c1 row=lane/4, col=(lane%4)*2; c2,c3 row+8)
    int rbase = m0 + warpM + (lane >> 2);
    int cbase = n0 + warpN + (lane & 3) * 2;
    #pragma unroll
    for (int mi = 0; mi < 4; mi++) {
        #pragma unroll
        for (int ni = 0; ni < 8; ni++) {
            float* p0 = out + (size_t)(rbase + mi * 16) * NDIM + cbase + ni * 8;
            float* p1 = p0 + 8 * NDIM;
            *reinterpret_cast<float2*>(p0) = make_float2(acc[mi][ni][0], acc[mi][ni][1]);
            *reinterpret_cast<float2*>(p1) = make_float2(acc[mi][ni][2], acc[mi][ni][3]);
        }
    }
}

// ---------------- launch -----------------------------------------------------
extern "C" void kernel_launch(void* const* d_in, const int* in_sizes, int n_in,
                              void* d_out, int out_size) {
    const float* A = (const float*)d_in[0];   // [4096, 4096] f32
    const float* s = (const float*)d_in[1];   // [32, 4096] f32
    const int* q = (const int*)d_in[2];       // [4096, 512] i32
    float* out = (float*)d_out;               // [4096, 4096] f32

    convert_A_kernel<<<8192, 256>>>(reinterpret_cast<const float4*>(A));
    dequant_W_kernel<<<dim3(KDIM / 64, NDIM / 64), 256>>>(q, s);

    cudaFuncSetAttribute(gemm_kernel, cudaFuncAttributeMaxDynamicSharedMemorySize,
                         SMEM_TOTAL);
    gemm_kernel<<<dim3(NDIM / BN, MDIM / BM), 256, SMEM_TOTAL>>>(out);
}

// round 5
// speedup vs baseline: 1.1864x; 1.1864x over previous
#include <cuda_runtime.h>
#include <cuda_fp16.h>
#include <cstdint>

// Problem dims (fixed by the dataset)
#define MDIM 4096
#define NDIM 4096
#define KDIM 4096
#define GS   128

// ---------------- scratch (allocation-free rule: __device__ globals) --------
__device__ __half g_Ah[(size_t)MDIM * KDIM];   // A in fp16, row-major [M,K]
__device__ __half g_Wt[(size_t)NDIM * KDIM];   // W^T in fp16, row-major [N,K]

// ---------------- helpers ----------------------------------------------------
__device__ __forceinline__ uint32_t smem_u32(const void* p) {
    uint32_t a;
    asm("{ .reg .u64 t; cvta.to.shared.u64 t, %1; cvt.u32.u64 %0, t; }"
        : "=r"(a) : "l"(p));
    return a;
}

__device__ __forceinline__ uint32_t sw128(uint32_t o) {
    return o ^ ((o >> 3) & 0x70);
}

#define CP_ASYNC16(dst, src) \
    asm volatile("cp.async.cg.shared.global [%0], [%1], 16;" :: "r"(dst), "l"(src) : "memory")
#define CP_COMMIT() asm volatile("cp.async.commit_group;" ::: "memory")
template <int N>
__device__ __forceinline__ void cp_wait() {
    asm volatile("cp.async.wait_group %0;" :: "n"(N) : "memory");
}

__device__ __forceinline__ void ldsm_x4(uint32_t (&r)[4], uint32_t addr) {
    asm volatile("ldmatrix.sync.aligned.m8n8.x4.shared.b16 {%0,%1,%2,%3}, [%4];"
                 : "=r"(r[0]), "=r"(r[1]), "=r"(r[2]), "=r"(r[3]) : "r"(addr));
}

__device__ __forceinline__ void mma_16816(float (&d)[4], const uint32_t (&a)[4],
                                          const uint32_t b0, const uint32_t b1) {
    asm volatile(
        "mma.sync.aligned.m16n8k16.row.col.f32.f16.f16.f32 "
        "{%0,%1,%2,%3}, {%4,%5,%6,%7}, {%8,%9}, {%0,%1,%2,%3};"
        : "+f"(d[0]), "+f"(d[1]), "+f"(d[2]), "+f"(d[3])
        : "r"(a[0]), "r"(a[1]), "r"(a[2]), "r"(a[3]), "r"(b0), "r"(b1));
}

// ---------------- kernel 1: A fp32 -> fp16 ----------------------------------
__global__ void __launch_bounds__(256) convert_A_kernel(const float4* __restrict__ A) {
    size_t i = (size_t)blockIdx.x * blockDim.x + threadIdx.x;  // 2M threads, 8 floats each
    float4 f0 = A[2 * i];
    float4 f1 = A[2 * i + 1];
    __half2 h[4];
    h[0] = __floats2half2_rn(f0.x, f0.y);
    h[1] = __floats2half2_rn(f0.z, f0.w);
    h[2] = __floats2half2_rn(f1.x, f1.y);
    h[3] = __floats2half2_rn(f1.z, f1.w);
    *reinterpret_cast<uint4*>(g_Ah + 8 * i) = *reinterpret_cast<uint4*>(h);
}

// ---------------- kernel 2: dequant + transpose to Wt[n][k] fp16 ------------
__global__ void __launch_bounds__(256) dequant_W_kernel(const int* __restrict__ q,
                                                        const float* __restrict__ s) {
    __shared__ float s_sc[64];
    __shared__ __half s_t[64][72];  // [n_local][k_local], padded

    int k0 = blockIdx.x * 64;
    int n0 = blockIdx.y * 64;
    int t = threadIdx.x;

    if (t < 64) s_sc[t] = s[(size_t)(k0 / GS) * NDIM + n0 + t];
    __syncthreads();

    // 64 k-rows x 8 q-words (8 nibbles each) = 512 words; 2 per thread
    #pragma unroll
    for (int it = 0; it < 2; it++) {
        int v = t + it * 256;
        int kl = v >> 3;
        int w = v & 7;
        uint32_t qw = (uint32_t)q[(size_t)(k0 + kl) * (NDIM / 8) + (n0 >> 3) + w];
        #pragma unroll
        for (int b = 0; b < 8; b++) {
            int nib = (int)((qw >> (4 * b)) & 0xFu);
            float val = (float)(nib - 8) * s_sc[w * 8 + b];
            s_t[w * 8 + b][kl] = __float2half_rn(val);
        }
    }
    __syncthreads();

    // coalesced write of Wt rows: 64 rows x 128B; each thread writes 32B
    int nl = t >> 2;
    int c = (t & 3) * 16;
    const uint4* src = reinterpret_cast<const uint4*>(&s_t[nl][c]);
    uint4* dst = reinterpret_cast<uint4*>(&g_Wt[(size_t)(n0 + nl) * KDIM + k0 + c]);
    dst[0] = src[0];
    dst[1] = src[1];
}

// ---------------- kernel 3: HMMA f16 GEMM ------------------------------------
// CTA tile 128(M) x 128(N), BK=64, 2-stage cp.async pipeline, 8 warps (64x32 each).
// 2 CTAs per SM (64 KB SMEM, <=128 regs) so barrier/epilogue bubbles overlap.
static constexpr int BK = 64;
static constexpr int NSTAGES = 2;
static constexpr int NCHUNK = KDIM / BK;            // 64
static constexpr int TILE_BYTES = 128 * BK * 2;     // 16 KB per operand per stage
static constexpr uint32_t STAGE_BYTES = 2 * TILE_BYTES;          // 32 KB
static constexpr uint32_t SMEM_TOTAL = NSTAGES * STAGE_BYTES;    // 64 KB

__device__ __forceinline__ void load_stage(uint32_t sb, int stage, int chunk,
                                           int m0, int n0, int t) {
    uint32_t a_s = sb + stage * STAGE_BYTES;
    uint32_t b_s = a_s + TILE_BYTES;
    size_t kbase = (size_t)chunk * BK;
    #pragma unroll
    for (int j = 0; j < 4; j++) {
        int v = t + 256 * j;       // 0..1023
        int r = v >> 3;            // row 0..127
        int c = v & 7;             // 16B chunk within 128B row
        uint32_t off = sw128((uint32_t)(r * 128 + c * 16));
        const __half* asrc = g_Ah + (size_t)(m0 + r) * KDIM + kbase + c * 8;
        const __half* bsrc = g_Wt + (size_t)(n0 + r) * KDIM + kbase + c * 8;
        CP_ASYNC16(a_s + off, asrc);
        CP_ASYNC16(b_s + off, bsrc);
    }
}

__global__ void __launch_bounds__(256, 2)
gemm_kernel(float* __restrict__ out) {
    extern __shared__ char smem[];
    uint32_t sb = smem_u32(smem);
    int t = threadIdx.x;
    int wid = t >> 5;
    int lane = t & 31;
    int n0 = blockIdx.x * 128;
    int m0 = blockIdx.y * 128;

    // warp tiling: 2 (M) x 4 (N) warps; warp tile 64 x 32
    int warpM = (wid & 1) * 64;
    int warpN = (wid >> 1) * 32;

    // per-lane ldmatrix address components
    int tt = lane >> 3;        // matrix index within x4
    int lr = lane & 7;         // row within 8x8 matrix
    // A frag x4: tiles (m+0,k+0),(m+8,k+0),(m+0,k+16B),(m+8,k+16B)
    int arow = warpM + (tt & 1) * 8 + lr;
    int akoff = (tt >> 1) * 16;       // bytes
    // B frag x4: tiles (n+0,k+0),(n+0,k+16B),(n+8,k+0),(n+8,k+16B)
    int brow = warpN + (tt >> 1) * 8 + lr;
    int bkoff = (tt & 1) * 16;        // bytes

    float acc[4][4][4];
    #pragma unroll
    for (int mi = 0; mi < 4; mi++)
        #pragma unroll
        for (int ni = 0; ni < 4; ni++)
            #pragma unroll
            for (int e = 0; e < 4; e++) acc[mi][ni][e] = 0.0f;

    // prologue: fill stage 0
    load_stage(sb, 0, 0, m0, n0, t);
    CP_COMMIT();

    for (int i = 0; i < NCHUNK; i++) {
        if (i + 1 < NCHUNK) {
            load_stage(sb, (i + 1) & 1, i + 1, m0, n0, t);
        }
        CP_COMMIT();
        cp_wait<1>();             // chunk i resident
        __syncthreads();

        uint32_t a_s = sb + (i & 1) * STAGE_BYTES;
        uint32_t b_s = a_s + TILE_BYTES;

        #pragma unroll
        for (int kk = 0; kk < 4; kk++) {
            uint32_t afrag[4][4];
            #pragma unroll
            for (int mi = 0; mi < 4; mi++) {
                uint32_t off = sw128((uint32_t)((arow + mi * 16) * 128 + kk * 32 + akoff));
                ldsm_x4(afrag[mi], a_s + off);
            }
            uint32_t bfrag[2][4];
            #pragma unroll
            for (int np = 0; np < 2; np++) {
                uint32_t off = sw128((uint32_t)((brow + np * 16) * 128 + kk * 32 + bkoff));
                ldsm_x4(bfrag[np], b_s + off);
            }
            #pragma unroll
            for (int mi = 0; mi < 4; mi++) {
                #pragma unroll
                for (int ni = 0; ni < 4; ni++) {
                    mma_16816(acc[mi][ni], afrag[mi],
                              bfrag[ni >> 1][(ni & 1) * 2],
                              bfrag[ni >> 1][(ni & 1) * 2 + 1]);
                }
            }
        }
        __syncthreads();
    }

    // epilogue: direct gmem writes (accum layout: c0,c1 row=lane/4, col=(lane%4)*2; c2,c3 row+8)
    int rbase = m0 + warpM + (lane >> 2);
    int cbase = n0 + warpN + (lane & 3) * 2;
    #pragma unroll
    for (int mi = 0; mi < 4; mi++) {
        #pragma unroll
        for (int ni = 0; ni < 4; ni++) {
            float* p0 = out + (size_t)(rbase + mi * 16) * NDIM + cbase + ni * 8;
            float* p1 = p0 + 8 * NDIM;
            *reinterpret_cast<float2*>(p0) = make_float2(acc[mi][ni][0], acc[mi][ni][1]);
            *reinterpret_cast<float2*>(p1) = make_float2(acc[mi][ni][2], acc[mi][ni][3]);
        }
    }
}

// ---------------- launch -----------------------------------------------------
extern "C" void kernel_launch(void* const* d_in, const int* in_sizes, int n_in,
                              void* d_out, int out_size) {
    const float* A = (const float*)d_in[0];   // [4096, 4096] f32
    const float* s = (const float*)d_in[1];   // [32, 4096] f32
    const int* q = (const int*)d_in[2];       // [4096, 512] i32
    float* out = (float*)d_out;               // [4096, 4096] f32

    convert_A_kernel<<<8192, 256>>>(reinterpret_cast<const float4*>(A));
    dequant_W_kernel<<<dim3(KDIM / 64, NDIM / 64), 256>>>(q, s);

    cudaFuncSetAttribute(gemm_kernel, cudaFuncAttributeMaxDynamicSharedMemorySize,
                         SMEM_TOTAL);
    gemm_kernel<<<dim3(NDIM / 128, MDIM / 128), 256, SMEM_TOTAL>>>(out);
}

// round 6
// speedup vs baseline: 1.2183x; 1.0269x over previous
#include <cuda_runtime.h>
#include <cuda_fp16.h>
#include <cstdint>

// Problem dims (fixed by the dataset)
#define MDIM 4096
#define NDIM 4096
#define KDIM 4096
#define GS   128

// ---------------- scratch (allocation-free rule: __device__ globals) --------
__device__ __half g_Ah[(size_t)MDIM * KDIM];   // A in fp16, row-major [M,K]
__device__ __half g_Wt[(size_t)NDIM * KDIM];   // W^T in fp16, row-major [N,K]

// ---------------- helpers ----------------------------------------------------
__device__ __forceinline__ uint32_t smem_u32(const void* p) {
    uint32_t a;
    asm("{ .reg .u64 t; cvta.to.shared.u64 t, %1; cvt.u32.u64 %0, t; }"
        : "=r"(a) : "l"(p));
    return a;
}

__device__ __forceinline__ uint32_t sw128(uint32_t o) {
    return o ^ ((o >> 3) & 0x70);
}

#define CP_ASYNC16(dst, src) \
    asm volatile("cp.async.cg.shared.global [%0], [%1], 16;" :: "r"(dst), "l"(src) : "memory")
#define CP_COMMIT() asm volatile("cp.async.commit_group;" ::: "memory")
template <int N>
__device__ __forceinline__ void cp_wait() {
    asm volatile("cp.async.wait_group %0;" :: "n"(N) : "memory");
}

__device__ __forceinline__ void ldsm_x4(uint32_t (&r)[4], uint32_t addr) {
    asm volatile("ldmatrix.sync.aligned.m8n8.x4.shared.b16 {%0,%1,%2,%3}, [%4];"
                 : "=r"(r[0]), "=r"(r[1]), "=r"(r[2]), "=r"(r[3]) : "r"(addr));
}

__device__ __forceinline__ void mma_16816(float (&d)[4], const uint32_t (&a)[4],
                                          const uint32_t b0, const uint32_t b1) {
    asm volatile(
        "mma.sync.aligned.m16n8k16.row.col.f32.f16.f16.f32 "
        "{%0,%1,%2,%3}, {%4,%5,%6,%7}, {%8,%9}, {%0,%1,%2,%3};"
        : "+f"(d[0]), "+f"(d[1]), "+f"(d[2]), "+f"(d[3])
        : "r"(a[0]), "r"(a[1]), "r"(a[2]), "r"(a[3]), "r"(b0), "r"(b1));
}

// ---------------- kernel 1: A fp32 -> fp16 ----------------------------------
__global__ void __launch_bounds__(256) convert_A_kernel(const float4* __restrict__ A) {
    size_t i = (size_t)blockIdx.x * blockDim.x + threadIdx.x;  // 2M threads, 8 floats each
    float4 f0 = A[2 * i];
    float4 f1 = A[2 * i + 1];
    __half2 h[4];
    h[0] = __floats2half2_rn(f0.x, f0.y);
    h[1] = __floats2half2_rn(f0.z, f0.w);
    h[2] = __floats2half2_rn(f1.x, f1.y);
    h[3] = __floats2half2_rn(f1.z, f1.w);
    *reinterpret_cast<uint4*>(g_Ah + 8 * i) = *reinterpret_cast<uint4*>(h);
}

// ---------------- kernel 2: dequant + transpose to Wt[n][k] fp16 ------------
__global__ void __launch_bounds__(256) dequant_W_kernel(const int* __restrict__ q,
                                                        const float* __restrict__ s) {
    __shared__ float s_sc[64];
    __shared__ __half s_t[64][72];  // [n_local][k_local], padded

    int k0 = blockIdx.x * 64;
    int n0 = blockIdx.y * 64;
    int t = threadIdx.x;

    if (t < 64) s_sc[t] = s[(size_t)(k0 / GS) * NDIM + n0 + t];
    __syncthreads();

    // 64 k-rows x 8 q-words (8 nibbles each) = 512 words; 2 per thread
    #pragma unroll
    for (int it = 0; it < 2; it++) {
        int v = t + it * 256;
        int kl = v >> 3;
        int w = v & 7;
        uint32_t qw = (uint32_t)q[(size_t)(k0 + kl) * (NDIM / 8) + (n0 >> 3) + w];
        #pragma unroll
        for (int b = 0; b < 8; b++) {
            int nib = (int)((qw >> (4 * b)) & 0xFu);
            float val = (float)(nib - 8) * s_sc[w * 8 + b];
            s_t[w * 8 + b][kl] = __float2half_rn(val);
        }
    }
    __syncthreads();

    // coalesced write of Wt rows: 64 rows x 128B; each thread writes 32B
    int nl = t >> 2;
    int c = (t & 3) * 16;
    const uint4* src = reinterpret_cast<const uint4*>(&s_t[nl][c]);
    uint4* dst = reinterpret_cast<uint4*>(&g_Wt[(size_t)(n0 + nl) * KDIM + k0 + c]);
    dst[0] = src[0];
    dst[1] = src[1];
}

// ---------------- kernel 3: HMMA f16 GEMM ------------------------------------
// CTA tile 128(M) x 128(N), BK=64, 3-stage cp.async pipeline, 8 warps (64x32 each).
// 2 CTAs per SM (96 KB SMEM each, <=128 regs); ONE __syncthreads per chunk.
static constexpr int BK = 64;
static constexpr int NSTAGES = 3;
static constexpr int NCHUNK = KDIM / BK;            // 64
static constexpr int TILE_BYTES = 128 * BK * 2;     // 16 KB per operand per stage
static constexpr uint32_t STAGE_BYTES = 2 * TILE_BYTES;          // 32 KB
static constexpr uint32_t SMEM_TOTAL = NSTAGES * STAGE_BYTES;    // 96 KB

__device__ __forceinline__ void load_stage(uint32_t sb, int stage, int chunk,
                                           int m0, int n0, int t) {
    uint32_t a_s = sb + stage * STAGE_BYTES;
    uint32_t b_s = a_s + TILE_BYTES;
    size_t kbase = (size_t)chunk * BK;
    #pragma unroll
    for (int j = 0; j < 4; j++) {
        int v = t + 256 * j;       // 0..1023
        int r = v >> 3;            // row 0..127
        int c = v & 7;             // 16B chunk within 128B row
        uint32_t off = sw128((uint32_t)(r * 128 + c * 16));
        const __half* asrc = g_Ah + (size_t)(m0 + r) * KDIM + kbase + c * 8;
        const __half* bsrc = g_Wt + (size_t)(n0 + r) * KDIM + kbase + c * 8;
        CP_ASYNC16(a_s + off, asrc);
        CP_ASYNC16(b_s + off, bsrc);
    }
}

__global__ void __launch_bounds__(256, 2)
gemm_kernel(float* __restrict__ out) {
    extern __shared__ char smem[];
    uint32_t sb = smem_u32(smem);
    int t = threadIdx.x;
    int wid = t >> 5;
    int lane = t & 31;
    int n0 = blockIdx.x * 128;
    int m0 = blockIdx.y * 128;

    // warp tiling: 2 (M) x 4 (N) warps; warp tile 64 x 32
    int warpM = (wid & 1) * 64;
    int warpN = (wid >> 1) * 32;

    // per-lane ldmatrix address components
    int tt = lane >> 3;        // matrix index within x4
    int lr = lane & 7;         // row within 8x8 matrix
    // A frag x4: tiles (m+0,k+0),(m+8,k+0),(m+0,k+16B),(m+8,k+16B)
    int arow = warpM + (tt & 1) * 8 + lr;
    int akoff = (tt >> 1) * 16;       // bytes
    // B frag x4: tiles (n+0,k+0),(n+0,k+16B),(n+8,k+0),(n+8,k+16B)
    int brow = warpN + (tt >> 1) * 8 + lr;
    int bkoff = (tt & 1) * 16;        // bytes

    float acc[4][4][4];
    #pragma unroll
    for (int mi = 0; mi < 4; mi++)
        #pragma unroll
        for (int ni = 0; ni < 4; ni++)
            #pragma unroll
            for (int e = 0; e < 4; e++) acc[mi][ni][e] = 0.0f;

    // prologue: fill stages 0,1 (chunks 0,1)
    load_stage(sb, 0, 0, m0, n0, t);
    CP_COMMIT();
    load_stage(sb, 1, 1, m0, n0, t);
    CP_COMMIT();

    int stage = 0;
    for (int i = 0; i < NCHUNK; i++) {
        cp_wait<NSTAGES - 2>();   // chunk i resident (per-thread)
        __syncthreads();          // all threads' stage-i data visible; stage (i+2)%3 free

        // issue prefetch for chunk i+2 into the just-freed stage
        int pf = i + NSTAGES - 1;
        if (pf < NCHUNK) {
            int pstage = stage + 2 >= NSTAGES ? stage + 2 - NSTAGES : stage + 2;
            load_stage(sb, pstage, pf, m0, n0, t);
        }
        CP_COMMIT();

        uint32_t a_s = sb + stage * STAGE_BYTES;
        uint32_t b_s = a_s + TILE_BYTES;

        #pragma unroll
        for (int kk = 0; kk < 4; kk++) {
            uint32_t afrag[4][4];
            #pragma unroll
            for (int mi = 0; mi < 4; mi++) {
                uint32_t off = sw128((uint32_t)((arow + mi * 16) * 128 + kk * 32 + akoff));
                ldsm_x4(afrag[mi], a_s + off);
            }
            uint32_t bfrag[2][4];
            #pragma unroll
            for (int np = 0; np < 2; np++) {
                uint32_t off = sw128((uint32_t)((brow + np * 16) * 128 + kk * 32 + bkoff));
                ldsm_x4(bfrag[np], b_s + off);
            }
            #pragma unroll
            for (int mi = 0; mi < 4; mi++) {
                #pragma unroll
                for (int ni = 0; ni < 4; ni++) {
                    mma_16816(acc[mi][ni], afrag[mi],
                              bfrag[ni >> 1][(ni & 1) * 2],
                              bfrag[ni >> 1][(ni & 1) * 2 + 1]);
                }
            }
        }

        stage++;
        if (stage == NSTAGES) stage = 0;
    }

    // epilogue: direct gmem writes (accum layout: c0,c1 row=lane/4, col=(lane%4)*2; c2,c3 row+8)
    int rbase = m0 + warpM + (lane >> 2);
    int cbase = n0 + warpN + (lane & 3) * 2;
    #pragma unroll
    for (int mi = 0; mi < 4; mi++) {
        #pragma unroll
        for (int ni = 0; ni < 4; ni++) {
            float* p0 = out + (size_t)(rbase + mi * 16) * NDIM + cbase + ni * 8;
            float* p1 = p0 + 8 * NDIM;
            *reinterpret_cast<float2*>(p0) = make_float2(acc[mi][ni][0], acc[mi][ni][1]);
            *reinterpret_cast<float2*>(p1) = make_float2(acc[mi][ni][2], acc[mi][ni][3]);
        }
    }
}

// ---------------- launch -----------------------------------------------------
extern "C" void kernel_launch(void* const* d_in, const int* in_sizes, int n_in,
                              void* d_out, int out_size) {
    const float* A = (const float*)d_in[0];   // [4096, 4096] f32
    const float* s = (const float*)d_in[1];   // [32, 4096] f32
    const int* q = (const int*)d_in[2];       // [4096, 512] i32
    float* out = (float*)d_out;               // [4096, 4096] f32

    convert_A_kernel<<<8192, 256>>>(reinterpret_cast<const float4*>(A));
    dequant_W_kernel<<<dim3(KDIM / 64, NDIM / 64), 256>>>(q, s);

    cudaFuncSetAttribute(gemm_kernel, cudaFuncAttributeMaxDynamicSharedMemorySize,
                         SMEM_TOTAL);
    gemm_kernel<<<dim3(NDIM / 128, MDIM / 128), 256, SMEM_TOTAL>>>(out);
}

// round 7
// speedup vs baseline: 1.2288x; 1.0086x over previous
#include <cuda_runtime.h>
#include <cuda_fp16.h>
#include <cstdint>

// Problem dims (fixed by the dataset)
#define MDIM 4096
#define NDIM 4096
#define KDIM 4096
#define GS   128

// ---------------- scratch (allocation-free rule: __device__ globals) --------
__device__ __half g_Ah[(size_t)MDIM * KDIM];   // A in fp16, row-major [M,K]
__device__ __half g_Wt[(size_t)NDIM * KDIM];   // W^T in fp16, row-major [N,K]

// ---------------- helpers ----------------------------------------------------
__device__ __forceinline__ uint32_t smem_u32(const void* p) {
    uint32_t a;
    asm("{ .reg .u64 t; cvta.to.shared.u64 t, %1; cvt.u32.u64 %0, t; }"
        : "=r"(a) : "l"(p));
    return a;
}

__device__ __forceinline__ uint32_t sw128(uint32_t o) {
    return o ^ ((o >> 3) & 0x70);
}

#define CP_ASYNC16(dst, src) \
    asm volatile("cp.async.cg.shared.global [%0], [%1], 16;" :: "r"(dst), "l"(src) : "memory")
#define CP_COMMIT() asm volatile("cp.async.commit_group;" ::: "memory")
template <int N>
__device__ __forceinline__ void cp_wait() {
    asm volatile("cp.async.wait_group %0;" :: "n"(N) : "memory");
}

__device__ __forceinline__ void ldsm_x4(uint32_t (&r)[4], uint32_t addr) {
    asm volatile("ldmatrix.sync.aligned.m8n8.x4.shared.b16 {%0,%1,%2,%3}, [%4];"
                 : "=r"(r[0]), "=r"(r[1]), "=r"(r[2]), "=r"(r[3]) : "r"(addr));
}

__device__ __forceinline__ void mma_16816(float (&d)[4], const uint32_t (&a)[4],
                                          const uint32_t b0, const uint32_t b1) {
    asm volatile(
        "mma.sync.aligned.m16n8k16.row.col.f32.f16.f16.f32 "
        "{%0,%1,%2,%3}, {%4,%5,%6,%7}, {%8,%9}, {%0,%1,%2,%3};"
        : "+f"(d[0]), "+f"(d[1]), "+f"(d[2]), "+f"(d[3])
        : "r"(a[0]), "r"(a[1]), "r"(a[2]), "r"(a[3]), "r"(b0), "r"(b1));
}

// ---------------- kernel 1: fused prep ---------------------------------------
// Blocks [0, 8192): A fp32 -> fp16.
// Blocks [8192, 12288): dequant+transpose q -> Wt[n][k] fp16.
// Both phases are DRAM-bound; fusing them into one grid overlaps their traffic.
static constexpr int CONV_BLOCKS = 8192;                       // 8192*256*8 halfs = 16M
static constexpr int DEQ_BLOCKS = (KDIM / 64) * (NDIM / 64);   // 4096
__global__ void __launch_bounds__(256) prep_kernel(const float4* __restrict__ A,
                                                   const int* __restrict__ q,
                                                   const float* __restrict__ s) {
    int t = threadIdx.x;
    if (blockIdx.x < CONV_BLOCKS) {
        size_t i = (size_t)blockIdx.x * 256 + t;   // 8 floats each
        float4 f0 = A[2 * i];
        float4 f1 = A[2 * i + 1];
        __half2 h[4];
        h[0] = __floats2half2_rn(f0.x, f0.y);
        h[1] = __floats2half2_rn(f0.z, f0.w);
        h[2] = __floats2half2_rn(f1.x, f1.y);
        h[3] = __floats2half2_rn(f1.z, f1.w);
        *reinterpret_cast<uint4*>(g_Ah + 8 * i) = *reinterpret_cast<uint4*>(h);
        return;
    }

    __shared__ float s_sc[64];
    __shared__ __half s_t[64][72];  // [n_local][k_local], padded

    int b = blockIdx.x - CONV_BLOCKS;
    int k0 = (b & 63) * 64;
    int n0 = (b >> 6) * 64;

    if (t < 64) s_sc[t] = s[(size_t)(k0 / GS) * NDIM + n0 + t];
    __syncthreads();

    // 64 k-rows x 8 q-words (8 nibbles each) = 512 words; 2 per thread
    #pragma unroll
    for (int it = 0; it < 2; it++) {
        int v = t + it * 256;
        int kl = v >> 3;
        int w = v & 7;
        uint32_t qw = (uint32_t)q[(size_t)(k0 + kl) * (NDIM / 8) + (n0 >> 3) + w];
        #pragma unroll
        for (int bb = 0; bb < 8; bb++) {
            int nib = (int)((qw >> (4 * bb)) & 0xFu);
            float val = (float)(nib - 8) * s_sc[w * 8 + bb];
            s_t[w * 8 + bb][kl] = __float2half_rn(val);
        }
    }
    __syncthreads();

    // coalesced write of Wt rows: 64 rows x 128B; each thread writes 32B
    int nl = t >> 2;
    int c = (t & 3) * 16;
    const uint4* src = reinterpret_cast<const uint4*>(&s_t[nl][c]);
    uint4* dst = reinterpret_cast<uint4*>(&g_Wt[(size_t)(n0 + nl) * KDIM + k0 + c]);
    dst[0] = src[0];
    dst[1] = src[1];
}

// ---------------- kernel 2: HMMA f16 GEMM ------------------------------------
// CTA tile 128(M) x 128(N), BK=64, 3-stage cp.async pipeline, 8 warps (64x32 each).
// 2 CTAs per SM (96 KB SMEM each, <=128 regs); ONE __syncthreads per chunk.
static constexpr int BK = 64;
static constexpr int NSTAGES = 3;
static constexpr int NCHUNK = KDIM / BK;            // 64
static constexpr int TILE_BYTES = 128 * BK * 2;     // 16 KB per operand per stage
static constexpr uint32_t STAGE_BYTES = 2 * TILE_BYTES;          // 32 KB
static constexpr uint32_t SMEM_TOTAL = NSTAGES * STAGE_BYTES;    // 96 KB

__device__ __forceinline__ void load_stage(uint32_t sb, int stage, int chunk,
                                           int m0, int n0, int t) {
    uint32_t a_s = sb + stage * STAGE_BYTES;
    uint32_t b_s = a_s + TILE_BYTES;
    size_t kbase = (size_t)chunk * BK;
    #pragma unroll
    for (int j = 0; j < 4; j++) {
        int v = t + 256 * j;       // 0..1023
        int r = v >> 3;            // row 0..127
        int c = v & 7;             // 16B chunk within 128B row
        uint32_t off = sw128((uint32_t)(r * 128 + c * 16));
        const __half* asrc = g_Ah + (size_t)(m0 + r) * KDIM + kbase + c * 8;
        const __half* bsrc = g_Wt + (size_t)(n0 + r) * KDIM + kbase + c * 8;
        CP_ASYNC16(a_s + off, asrc);
        CP_ASYNC16(b_s + off, bsrc);
    }
}

__global__ void __launch_bounds__(256, 2)
gemm_kernel(float* __restrict__ out) {
    extern __shared__ char smem[];
    uint32_t sb = smem_u32(smem);
    int t = threadIdx.x;
    int wid = t >> 5;
    int lane = t & 31;
    int n0 = blockIdx.x * 128;
    int m0 = blockIdx.y * 128;

    // warp tiling: 2 (M) x 4 (N) warps; warp tile 64 x 32
    int warpM = (wid & 1) * 64;
    int warpN = (wid >> 1) * 32;

    // per-lane ldmatrix address components
    int tt = lane >> 3;        // matrix index within x4
    int lr = lane & 7;         // row within 8x8 matrix
    // A frag x4: tiles (m+0,k+0),(m+8,k+0),(m+0,k+16B),(m+8,k+16B)
    int arow = warpM + (tt & 1) * 8 + lr;
    int akoff = (tt >> 1) * 16;       // bytes
    // B frag x4: tiles (n+0,k+0),(n+0,k+16B),(n+8,k+0),(n+8,k+16B)
    int brow = warpN + (tt >> 1) * 8 + lr;
    int bkoff = (tt & 1) * 16;        // bytes

    float acc[4][4][4];
    #pragma unroll
    for (int mi = 0; mi < 4; mi++)
        #pragma unroll
        for (int ni = 0; ni < 4; ni++)
            #pragma unroll
            for (int e = 0; e < 4; e++) acc[mi][ni][e] = 0.0f;

    // prologue: fill stages 0,1 (chunks 0,1)
    load_stage(sb, 0, 0, m0, n0, t);
    CP_COMMIT();
    load_stage(sb, 1, 1, m0, n0, t);
    CP_COMMIT();

    int stage = 0;
    for (int i = 0; i < NCHUNK; i++) {
        cp_wait<NSTAGES - 2>();   // chunk i resident (per-thread)
        __syncthreads();          // all threads' stage-i data visible; stage (i+2)%3 free

        // issue prefetch for chunk i+2 into the just-freed stage
        int pf = i + NSTAGES - 1;
        if (pf < NCHUNK) {
            int pstage = stage + 2 >= NSTAGES ? stage + 2 - NSTAGES : stage + 2;
            load_stage(sb, pstage, pf, m0, n0, t);
        }
        CP_COMMIT();

        uint32_t a_s = sb + stage * STAGE_BYTES;
        uint32_t b_s = a_s + TILE_BYTES;

        #pragma unroll
        for (int kk = 0; kk < 4; kk++) {
            uint32_t afrag[4][4];
            #pragma unroll
            for (int mi = 0; mi < 4; mi++) {
                uint32_t off = sw128((uint32_t)((arow + mi * 16) * 128 + kk * 32 + akoff));
                ldsm_x4(afrag[mi], a_s + off);
            }
            uint32_t bfrag[2][4];
            #pragma unroll
            for (int np = 0; np < 2; np++) {
                uint32_t off = sw128((uint32_t)((brow + np * 16) * 128 + kk * 32 + bkoff));
                ldsm_x4(bfrag[np], b_s + off);
            }
            #pragma unroll
            for (int mi = 0; mi < 4; mi++) {
                #pragma unroll
                for (int ni = 0; ni < 4; ni++) {
                    mma_16816(acc[mi][ni], afrag[mi],
                              bfrag[ni >> 1][(ni & 1) * 2],
                              bfrag[ni >> 1][(ni & 1) * 2 + 1]);
                }
            }
        }

        stage++;
        if (stage == NSTAGES) stage = 0;
    }

    // epilogue: direct gmem writes (accum layout: c0,c1 row=lane/4, col=(lane%4)*2; c2,c3 row+8)
    int rbase = m0 + warpM + (lane >> 2);
    int cbase = n0 + warpN + (lane & 3) * 2;
    #pragma unroll
    for (int mi = 0; mi < 4; mi++) {
        #pragma unroll
        for (int ni = 0; ni < 4; ni++) {
            float* p0 = out + (size_t)(rbase + mi * 16) * NDIM + cbase + ni * 8;
            float* p1 = p0 + 8 * NDIM;
            *reinterpret_cast<float2*>(p0) = make_float2(acc[mi][ni][0], acc[mi][ni][1]);
            *reinterpret_cast<float2*>(p1) = make_float2(acc[mi][ni][2], acc[mi][ni][3]);
        }
    }
}

// ---------------- launch -----------------------------------------------------
extern "C" void kernel_launch(void* const* d_in, const int* in_sizes, int n_in,
                              void* d_out, int out_size) {
    const float* A = (const float*)d_in[0];   // [4096, 4096] f32
    const float* s = (const float*)d_in[1];   // [32, 4096] f32
    const int* q = (const int*)d_in[2];       // [4096, 512] i32
    float* out = (float*)d_out;               // [4096, 4096] f32

    prep_kernel<<<CONV_BLOCKS + DEQ_BLOCKS, 256>>>(
        reinterpret_cast<const float4*>(A), q, s);

    cudaFuncSetAttribute(gemm_kernel, cudaFuncAttributeMaxDynamicSharedMemorySize,
                         SMEM_TOTAL);
    gemm_kernel<<<dim3(NDIM / 128, MDIM / 128), 256, SMEM_TOTAL>>>(out);
}